// round 6
// baseline (speedup 1.0000x reference)
#include <cuda_runtime.h>
#include <math_constants.h>

// Problem shape (fixed by the dataset):
// x: (4, 128, 31, 32, 22) f32; w1,w2: (128,); b1,b2 scalars; top_k = 16
// out: (4, 16, 30, 32, 22) f32
#define NB   4
#define CC   128
#define SSZ  31
#define HW   704      // 32*22
#define SM1  30       // SSZ-1
#define NP   (NB*SM1) // 120 frame pairs
#define KK   16
#define NPIX (NB*SSZ*HW)   // 87296
#define NQ   (NPIX/4)      // 21824 quads = 32 * 682
#define FRM  (SSZ*HW)      // 21824 (elements per (n,c) channel slab)
#define LOG2E 1.4426950408889634f

// Scratch (allocation-free rule: __device__ globals)
__device__ float g_A[NPIX];   // a  = dot(x, w1) + b1 per pixel
__device__ float g_U[NPIX];   // u  = (dot(x, w2) + b2) * log2e per pixel

__device__ __forceinline__ float ex2f(float x) {
    float y;
    asm("ex2.approx.ftz.f32 %0, %1;" : "=f"(y) : "f"(x));
    return y;
}

// ---------------------------------------------------------------------------
// Kernel A v6: 1x1 conv (C->1), both weights, one pass over x (44.7 MB).
// Tile = 32 quads; block = 64 thr = 16 quad-lanes x 4 channel groups (32 ch).
// Grid 682 -> 4-5 blocks/SM, ~9% imbalance (vs 30% at tile=64quads/341blk).
// Two independent LDG.128 per channel iteration per thread (MLP).
// ---------------------------------------------------------------------------
__global__ __launch_bounds__(64)
void conv_kernel(const float* __restrict__ x,
                 const float* __restrict__ w1,
                 const float* __restrict__ w2,
                 const float* __restrict__ b1p,
                 const float* __restrict__ b2p) {
    __shared__ float  sw1[CC], sw2[CC];
    __shared__ float4 p1[3][32], p2[3][32];
    const int tid  = threadIdx.x;
    const int lane = tid & 15;      // quad lane within tile (0..15)
    const int grp  = tid >> 4;      // channel group 0..3
    sw1[tid] = w1[tid]; sw1[tid + 64] = w1[tid + 64];
    sw2[tid] = w2[tid]; sw2[tid + 64] = w2[tid + 64];
    __syncthreads();

    const int qA = blockIdx.x * 32 + lane;     // this lane's quads: qA, qA+16
    const int tA = qA * 4;
    const int tB = tA + 64;
    const int nA = tA / FRM;                   // tiles may straddle n: per-quad n
    const int nB = tB / FRM;
    // addr of (n, c, s, i) = t + (n*(CC-1) + c) * FRM
    const float* xA  = x + (size_t)(nA*(CC-1) + grp*32) * FRM + tA;
    const float* xB  = x + (size_t)(nB*(CC-1) + grp*32) * FRM + tB;
    const float* pw1 = sw1 + grp*32;
    const float* pw2 = sw2 + grp*32;

    float4 a1A = make_float4(0.f,0.f,0.f,0.f);
    float4 a2A = make_float4(0.f,0.f,0.f,0.f);
    float4 a1B = make_float4(0.f,0.f,0.f,0.f);
    float4 a2B = make_float4(0.f,0.f,0.f,0.f);
    #pragma unroll 8
    for (int c = 0; c < 32; ++c) {
        float4 vA = *reinterpret_cast<const float4*>(xA + (size_t)c * FRM);
        float4 vB = *reinterpret_cast<const float4*>(xB + (size_t)c * FRM);
        float u1 = pw1[c], u2 = pw2[c];
        a1A.x = fmaf(vA.x, u1, a1A.x); a1A.y = fmaf(vA.y, u1, a1A.y);
        a1A.z = fmaf(vA.z, u1, a1A.z); a1A.w = fmaf(vA.w, u1, a1A.w);
        a2A.x = fmaf(vA.x, u2, a2A.x); a2A.y = fmaf(vA.y, u2, a2A.y);
        a2A.z = fmaf(vA.z, u2, a2A.z); a2A.w = fmaf(vA.w, u2, a2A.w);
        a1B.x = fmaf(vB.x, u1, a1B.x); a1B.y = fmaf(vB.y, u1, a1B.y);
        a1B.z = fmaf(vB.z, u1, a1B.z); a1B.w = fmaf(vB.w, u1, a1B.w);
        a2B.x = fmaf(vB.x, u2, a2B.x); a2B.y = fmaf(vB.y, u2, a2B.y);
        a2B.z = fmaf(vB.z, u2, a2B.z); a2B.w = fmaf(vB.w, u2, a2B.w);
    }
    if (grp) {
        p1[grp-1][lane]      = a1A;  p1[grp-1][lane + 16] = a1B;
        p2[grp-1][lane]      = a2A;  p2[grp-1][lane + 16] = a2B;
    }
    __syncthreads();
    if (!grp) {
        const float b1 = *b1p, b2 = *b2p;
        #pragma unroll
        for (int g = 0; g < 3; ++g) {
            float4 u = p1[g][lane],      v = p2[g][lane];
            float4 r = p1[g][lane + 16], w = p2[g][lane + 16];
            a1A.x += u.x; a1A.y += u.y; a1A.z += u.z; a1A.w += u.w;
            a2A.x += v.x; a2A.y += v.y; a2A.z += v.z; a2A.w += v.w;
            a1B.x += r.x; a1B.y += r.y; a1B.z += r.z; a1B.w += r.w;
            a2B.x += w.x; a2B.y += w.y; a2B.z += w.z; a2B.w += w.w;
        }
        float4 oA1 = make_float4(a1A.x + b1, a1A.y + b1, a1A.z + b1, a1A.w + b1);
        float4 oB1 = make_float4(a1B.x + b1, a1B.y + b1, a1B.z + b1, a1B.w + b1);
        float4 oA2 = make_float4((a2A.x + b2)*LOG2E, (a2A.y + b2)*LOG2E,
                                 (a2A.z + b2)*LOG2E, (a2A.w + b2)*LOG2E);
        float4 oB2 = make_float4((a2B.x + b2)*LOG2E, (a2B.y + b2)*LOG2E,
                                 (a2B.z + b2)*LOG2E, (a2B.w + b2)*LOG2E);
        *reinterpret_cast<float4*>(g_A + tA) = oA1;
        *reinterpret_cast<float4*>(g_A + tB) = oB1;
        *reinterpret_cast<float4*>(g_U + tA) = oA2;
        *reinterpret_cast<float4*>(g_U + tB) = oB2;
    }
}

// ---------------------------------------------------------------------------
// Kernel B: fused partition sums + top/bottom-16 selection + softmax top-k.
// No max-shift needed: |a*u| <= ~30, exp2 cannot overflow, softmax is
// shift-invariant. One lane = one row i: S = sum_j exp2(a*u_j).
// Selection runs AFTER the MUFU-bound sum loop (warp0: top16 desc,
// warp1: bottom16 asc via negation) and hides in idle issue slots.
// Output mapping (torch .view semantics): row i's 16 rank-values occupy the
// contiguous range [16i, 16i+16) of the pair's flat output; 704 = 44*16 so
// the range never straddles a kq slice: kq = i/44, j0 = (16i) % 704.
// ---------------------------------------------------------------------------
__global__ __launch_bounds__(64)
void attn_kernel(float* __restrict__ out) {
    __shared__ float4 u4[HW/4];
    __shared__ float  selU[32];
    const int blk   = blockIdx.x;
    const int p     = blk / 11;
    const int chunk = blk % 11;           // 64-row chunk within the pair
    const int n = p / SM1, s = p % SM1;
    const int tid = threadIdx.x;

    float* u = reinterpret_cast<float*>(u4);
    const float* U = g_U + (n*SSZ + s + 1)*HW;
    for (int j = tid; j < HW; j += 64) u[j] = U[j];
    __syncthreads();

    const int   i = chunk*64 + tid;                   // row in [0, 704)
    const float a = g_A[(n*SSZ + s)*HW + i];

    float acc0 = 0.f, acc1 = 0.f, acc2 = 0.f, acc3 = 0.f;
    #pragma unroll 4
    for (int j = 0; j < HW/4; ++j) {
        float4 uu = u4[j];                            // broadcast LDS.128
        acc0 += ex2f(a * uu.x);
        acc1 += ex2f(a * uu.y);
        acc2 += ex2f(a * uu.z);
        acc3 += ex2f(a * uu.w);
    }
    const float inv = 1.0f / ((acc0 + acc1) + (acc2 + acc3));

    // ---- in-block selection: warp 0 -> top16 desc, warp 1 -> bottom16 asc
    {
        const int lane = tid & 31;
        const int wid  = tid >> 5;
        float v[22];
        #pragma unroll
        for (int q = 0; q < 22; ++q) v[q] = u[q*32 + lane];
        if (wid) {
            #pragma unroll
            for (int q = 0; q < 22; ++q) v[q] = -v[q];
        }
        float* outp = selU + wid*KK;
        for (int k = 0; k < KK; ++k) {
            float m = v[0];
            #pragma unroll
            for (int q = 1; q < 22; ++q) m = fmaxf(m, v[q]);
            #pragma unroll
            for (int off = 16; off > 0; off >>= 1)
                m = fmaxf(m, __shfl_xor_sync(0xffffffffu, m, off));
            bool mine = false;
            #pragma unroll
            for (int q = 0; q < 22; ++q) mine |= (v[q] == m);
            unsigned ball = __ballot_sync(0xffffffffu, mine);
            if (lane == (__ffs(ball) - 1)) {
                bool done = false;
                #pragma unroll
                for (int q = 0; q < 22; ++q)
                    if (!done && v[q] == m) { v[q] = -CUDART_INF_F; done = true; }
            }
            if (lane == 0) outp[k] = wid ? -m : m;
        }
    }
    __syncthreads();

    const float* selp = (a > 0.f) ? selU : (selU + KK);
    float vals[KK];
    #pragma unroll
    for (int k = 0; k < KK; ++k)
        vals[k] = ex2f(a * selp[k]) * inv;

    const int Lbase = i * KK;            // 16*i
    const int kq    = Lbase / HW;        // = i / 44
    const int j0    = Lbase % HW;
    float* op = out + (((size_t)(n*KK + kq))*SM1 + s)*HW + j0;
    float4* op4 = reinterpret_cast<float4*>(op);
    const float4* v4 = reinterpret_cast<const float4*>(vals);
    #pragma unroll
    for (int q = 0; q < 4; ++q)
        op4[q] = v4[q];
}

extern "C" void kernel_launch(void* const* d_in, const int* in_sizes, int n_in,
                              void* d_out, int out_size) {
    const float* x  = (const float*)d_in[0];
    const float* w1 = (const float*)d_in[1];
    const float* b1 = (const float*)d_in[2];
    const float* w2 = (const float*)d_in[3];
    const float* b2 = (const float*)d_in[4];
    float* out = (float*)d_out;

    conv_kernel<<<682, 64>>>(x, w1, w2, b1, b2);   // NQ = 32*682
    attn_kernel<<<NP*11, 64>>>(out);               // 1320 blocks
}